// round 1
// baseline (speedup 1.0000x reference)
#include <cuda_runtime.h>

// ---------------------------------------------------------------------------
// ODELayer: RK4 integration of a small MLP ODE, 256 steps, batch 1024.
// Rows are independent -> partition batch across CTAs, no inter-CTA sync.
// 128 CTAs x 8 rows each; 256 threads/CTA; fp32 with packed f32x2 FMA.
// Weights pre-transposed to [K][N] in __device__ scratch (read via L2).
// Activations in smem as row-pair-interleaved float2: act[p][k] = (row 2p, row 2p+1).
// ---------------------------------------------------------------------------

#define NU   32
#define NX   128
#define NF   256
#define NIN  160           // NX + NU
#define NT   256           // timesteps
#define NB   1024          // batch
#define ROWS 8             // rows per CTA
#define NCTA (NB / ROWS)   // 128
#define NTHREADS 256

// Transposed weight scratch (static device memory: allowed, no allocation)
__device__ float g_W1T[NIN * NF];
__device__ float g_WlT[NIN * NX];
__device__ float g_W2T[NF * NF];
__device__ float g_W3T[NF * NX];
__device__ float g_Wo1T[NX * NF];
__device__ float g_Wo2T[NF * NF];
__device__ float g_Wo3T[NF * NX];

using ull = unsigned long long;

__device__ __forceinline__ ull pack2(float w) {
    ull r;
    asm("mov.b64 %0, {%1, %1};" : "=l"(r) : "f"(w));
    return r;
}
__device__ __forceinline__ void fma2(ull &d, ull a, ull b) {
    // packed fp32x2 FMA: d.lo = a.lo*b.lo + d.lo ; d.hi = a.hi*b.hi + d.hi
    asm("fma.rn.f32x2 %0, %1, %2, %0;" : "+l"(d) : "l"(a), "l"(b));
}
__device__ __forceinline__ float2 u2f(ull v) {
    float2 r;
    asm("mov.b64 {%0, %1}, %2;" : "=f"(r.x), "=f"(r.y) : "l"(v));
    return r;
}

// N-wide layer (N == 256 == blockDim): thread n computes output column n for
// all 8 rows (4 row-pairs). src: [4][K] float2 (pair-interleaved), dst: [4][N].
template <int K, int N, bool RELU>
__device__ __forceinline__ void layerN(const float* __restrict__ WT,   // [K][N]
                                       const float* __restrict__ bias, // [N]
                                       const float2* __restrict__ src,
                                       float2* __restrict__ dst,
                                       int n) {
    ull a0, a1, a2, a3;
    {
        ull bb = pack2(bias[n]);
        a0 = bb; a1 = bb; a2 = bb; a3 = bb;
    }
    const float* wp = WT + n;
#pragma unroll 4
    for (int k = 0; k < K; k += 2) {
        ull w0 = pack2(__ldg(wp + (size_t)k * N));
        ull w1 = pack2(__ldg(wp + (size_t)(k + 1) * N));
        ulonglong2 z0 = *reinterpret_cast<const ulonglong2*>(src + 0 * K + k);
        ulonglong2 z1 = *reinterpret_cast<const ulonglong2*>(src + 1 * K + k);
        ulonglong2 z2 = *reinterpret_cast<const ulonglong2*>(src + 2 * K + k);
        ulonglong2 z3 = *reinterpret_cast<const ulonglong2*>(src + 3 * K + k);
        fma2(a0, z0.x, w0); fma2(a0, z0.y, w1);
        fma2(a1, z1.x, w0); fma2(a1, z1.y, w1);
        fma2(a2, z2.x, w0); fma2(a2, z2.y, w1);
        fma2(a3, z3.x, w0); fma2(a3, z3.y, w1);
    }
    float2 v0 = u2f(a0), v1 = u2f(a1), v2 = u2f(a2), v3 = u2f(a3);
    if (RELU) {
        v0.x = fmaxf(v0.x, 0.f); v0.y = fmaxf(v0.y, 0.f);
        v1.x = fmaxf(v1.x, 0.f); v1.y = fmaxf(v1.y, 0.f);
        v2.x = fmaxf(v2.x, 0.f); v2.y = fmaxf(v2.y, 0.f);
        v3.x = fmaxf(v3.x, 0.f); v3.y = fmaxf(v3.y, 0.f);
    }
    dst[0 * N + n] = v0; dst[1 * N + n] = v1;
    dst[2 * N + n] = v2; dst[3 * N + n] = v3;
}

// 128-wide layer with split-K over the two thread-halves.
// Contains internal __syncthreads (all 256 threads must call).
template <int K>
__device__ __forceinline__ void layer128(const float* __restrict__ WT,     // [K][NX]
                                         const float* __restrict__ bias,   // nullable
                                         const float2* __restrict__ src,   // [4][K]
                                         const float2* __restrict__ addsrc,// nullable [4][NX]
                                         float2* __restrict__ dst,         // [4][NX]
                                         float2* __restrict__ part,        // [4][NX]
                                         int tid) {
    const int n = tid & (NX - 1);
    const int half = tid >> 7;
    const int k0 = half * (K / 2);
    ull a0 = 0, a1 = 0, a2 = 0, a3 = 0;
    const float* wp = WT + n;
#pragma unroll 4
    for (int kk = 0; kk < K / 2; kk += 2) {
        int k = k0 + kk;
        ull w0 = pack2(__ldg(wp + (size_t)k * NX));
        ull w1 = pack2(__ldg(wp + (size_t)(k + 1) * NX));
        ulonglong2 z0 = *reinterpret_cast<const ulonglong2*>(src + 0 * K + k);
        ulonglong2 z1 = *reinterpret_cast<const ulonglong2*>(src + 1 * K + k);
        ulonglong2 z2 = *reinterpret_cast<const ulonglong2*>(src + 2 * K + k);
        ulonglong2 z3 = *reinterpret_cast<const ulonglong2*>(src + 3 * K + k);
        fma2(a0, z0.x, w0); fma2(a0, z0.y, w1);
        fma2(a1, z1.x, w0); fma2(a1, z1.y, w1);
        fma2(a2, z2.x, w0); fma2(a2, z2.y, w1);
        fma2(a3, z3.x, w0); fma2(a3, z3.y, w1);
    }
    if (half) {
        part[0 * NX + n] = u2f(a0); part[1 * NX + n] = u2f(a1);
        part[2 * NX + n] = u2f(a2); part[3 * NX + n] = u2f(a3);
    }
    __syncthreads();
    if (!half) {
        float b = bias ? bias[n] : 0.f;
        ull accs[4] = {a0, a1, a2, a3};
#pragma unroll
        for (int p = 0; p < 4; ++p) {
            float2 v = u2f(accs[p]);
            float2 q = part[p * NX + n];
            v.x += q.x + b; v.y += q.y + b;
            if (addsrc) {
                float2 av = addsrc[p * NX + n];
                v.x += av.x; v.y += av.y;
            }
            dst[p * NX + n] = v;
        }
    }
    __syncthreads();
}

__global__ void prep_kernel(const float* __restrict__ W_lin, const float* __restrict__ W1,
                            const float* __restrict__ W2, const float* __restrict__ W3,
                            const float* __restrict__ Wo1, const float* __restrict__ Wo2,
                            const float* __restrict__ Wo3) {
    int i0 = blockIdx.x * blockDim.x + threadIdx.x;
    int stride = gridDim.x * blockDim.x;
    for (int j = i0; j < NF * NIN; j += stride) { int n = j / NIN, k = j % NIN; g_W1T[k * NF + n] = W1[j]; }
    for (int j = i0; j < NX * NIN; j += stride) { int m = j / NIN, k = j % NIN; g_WlT[k * NX + m] = W_lin[j]; }
    for (int j = i0; j < NF * NF;  j += stride) { int n = j / NF,  k = j % NF;  g_W2T[k * NF + n] = W2[j]; }
    for (int j = i0; j < NX * NF;  j += stride) { int m = j / NF,  k = j % NF;  g_W3T[k * NX + m] = W3[j]; }
    for (int j = i0; j < NF * NX;  j += stride) { int n = j / NX,  k = j % NX;  g_Wo1T[k * NF + n] = Wo1[j]; }
    for (int j = i0; j < NF * NF;  j += stride) { int n = j / NF,  k = j % NF;  g_Wo2T[k * NF + n] = Wo2[j]; }
    for (int j = i0; j < NX * NF;  j += stride) { int m = j / NF,  k = j % NF;  g_Wo3T[k * NX + m] = Wo3[j]; }
}

__global__ void __launch_bounds__(NTHREADS, 1)
ode_kernel(const float* __restrict__ input,   // [NT][NB][NU]
           const float* __restrict__ x0,      // [1][NB][NX]
           const float* __restrict__ dtp,     // scalar
           const float* __restrict__ b1, const float* __restrict__ b2,
           const float* __restrict__ b3, const float* __restrict__ bo1,
           const float* __restrict__ bo2, const float* __restrict__ bo3,
           float* __restrict__ y_out,         // [NT][NB][NX]
           float* __restrict__ xf_out)        // [NB][NX]
{
    __shared__ __align__(16) float2 s_ze[4 * NIN];  // z = [x | u]
    __shared__ __align__(16) float2 s_h1[4 * NF];
    __shared__ __align__(16) float2 s_h2[4 * NF];
    __shared__ __align__(16) float2 s_lin[4 * NX];
    __shared__ __align__(16) float2 s_k[4 * NX];
    __shared__ __align__(16) float2 s_ks[4 * NX];
    __shared__ __align__(16) float2 s_x[4 * NX];
    __shared__ __align__(16) float2 s_part[4 * NX];

    const int tid = threadIdx.x;
    const int rowbase = blockIdx.x * ROWS;
    const float dt = *dtp;
    const float dth = 0.5f * dt;
    const float dt6 = dt * (1.0f / 6.0f);

    // load x0 (pair-interleave rows)
    for (int idx = tid; idx < ROWS * NX; idx += NTHREADS) {
        int r = idx >> 7, c = idx & (NX - 1);
        float v = x0[(size_t)(rowbase + r) * NX + c];
        ((float*)&s_x[(r >> 1) * NX + c])[r & 1] = v;
    }
    __syncthreads();

    for (int t = 0; t < NT; ++t) {
        // u -> tail of z (cols 128..159); persists across the 4 RK4 evals
        {
            int r = tid >> 5, c = tid & 31;
            float v = input[((size_t)t * NB + rowbase + r) * NU + c];
            ((float*)&s_ze[(r >> 1) * NIN + NX + c])[r & 1] = v;
        }
        // x -> head of z; zero ksum
        for (int idx = tid; idx < 4 * NX; idx += NTHREADS) {
            int p = idx >> 7, c = idx & (NX - 1);
            s_ze[p * NIN + c] = s_x[idx];
            s_ks[idx] = make_float2(0.f, 0.f);
        }
        __syncthreads();

        // ---- RK4: 4 evaluations of dx_net ----
#pragma unroll 1
        for (int e = 0; e < 4; ++e) {
            layerN<NIN, NF, true>(g_W1T, b1, s_ze, s_h1, tid);
            __syncthreads();
            layer128<NIN>(g_WlT, nullptr, s_ze, nullptr, s_lin, s_part, tid);
            layerN<NF, NF, true>(g_W2T, b2, s_h1, s_h2, tid);
            __syncthreads();
            layer128<NF>(g_W3T, b3, s_h2, s_lin, s_k, s_part, tid);  // k = lin + h2@W3T + b3

            const float we = (e == 1 || e == 2) ? 2.f : 1.f;
            const float ce = (e < 2) ? dth : dt;  // coef for next eval state
            for (int idx = tid; idx < 4 * NX; idx += NTHREADS) {
                float2 kv = s_k[idx];
                float2 s = s_ks[idx];
                s.x = fmaf(we, kv.x, s.x);
                s.y = fmaf(we, kv.y, s.y);
                s_ks[idx] = s;
                if (e < 3) {
                    int p = idx >> 7, c = idx & (NX - 1);
                    float2 xv = s_x[idx];
                    s_ze[p * NIN + c] = make_float2(fmaf(ce, kv.x, xv.x),
                                                    fmaf(ce, kv.y, xv.y));
                }
            }
            __syncthreads();
        }

        // x += dt/6 * (k1 + 2k2 + 2k3 + k4)
        for (int idx = tid; idx < 4 * NX; idx += NTHREADS) {
            float2 xv = s_x[idx], s = s_ks[idx];
            xv.x = fmaf(dt6, s.x, xv.x);
            xv.y = fmaf(dt6, s.y, xv.y);
            s_x[idx] = xv;
        }
        __syncthreads();

        // ---- out_net(x_new) ----
        layerN<NX, NF, true>(g_Wo1T, bo1, s_x, s_h1, tid);
        __syncthreads();
        layerN<NF, NF, true>(g_Wo2T, bo2, s_h1, s_h2, tid);
        __syncthreads();
        layer128<NF>(g_Wo3T, bo3, s_h2, nullptr, s_k, s_part, tid);  // y -> s_k

        // store y[t]
        for (int idx = tid; idx < ROWS * NX; idx += NTHREADS) {
            int r = idx >> 7, c = idx & (NX - 1);
            float v = ((const float*)&s_k[(r >> 1) * NX + c])[r & 1];
            y_out[((size_t)t * NB + rowbase + r) * NX + c] = v;
        }
        __syncthreads();
    }

    // store x_final
    for (int idx = tid; idx < ROWS * NX; idx += NTHREADS) {
        int r = idx >> 7, c = idx & (NX - 1);
        xf_out[(size_t)(rowbase + r) * NX + c] =
            ((const float*)&s_x[(r >> 1) * NX + c])[r & 1];
    }
}

extern "C" void kernel_launch(void* const* d_in, const int* in_sizes, int n_in,
                              void* d_out, int out_size) {
    const float* input = (const float*)d_in[0];
    const float* x_step = (const float*)d_in[1];
    const float* dtp   = (const float*)d_in[2];
    const float* W_lin = (const float*)d_in[3];
    const float* W1    = (const float*)d_in[4];
    const float* b1    = (const float*)d_in[5];
    const float* W2    = (const float*)d_in[6];
    const float* b2    = (const float*)d_in[7];
    const float* W3    = (const float*)d_in[8];
    const float* b3    = (const float*)d_in[9];
    const float* Wo1   = (const float*)d_in[10];
    const float* bo1   = (const float*)d_in[11];
    const float* Wo2   = (const float*)d_in[12];
    const float* bo2   = (const float*)d_in[13];
    const float* Wo3   = (const float*)d_in[14];
    const float* bo3   = (const float*)d_in[15];

    float* out = (float*)d_out;
    float* y_out  = out;                               // [NT][NB][NX]
    float* xf_out = out + (size_t)NT * NB * NX;        // [NB][NX]

    prep_kernel<<<256, 256>>>(W_lin, W1, W2, W3, Wo1, Wo2, Wo3);
    ode_kernel<<<NCTA, NTHREADS>>>(input, x_step, dtp,
                                   b1, b2, b3, bo1, bo2, bo3,
                                   y_out, xf_out);
}

// round 4
// speedup vs baseline: 1.3268x; 1.3268x over previous
#include <cuda_runtime.h>

// ---------------------------------------------------------------------------
// ODELayer: RK4 integration of a small MLP ODE, 256 steps, batch 1024.
// Rows independent -> 128 CTAs x 8 rows, no inter-CTA sync.
// Round 2: 512 threads/CTA with split-K layers (2-way for N=256 layers,
// 4-way for N=128 layers) + smem partial reduction. Doubles warps/SMSP to
// hide L2 weight-load latency. Weights read once per CTA per layer (L2/L1).
// fp32 with packed f32x2 FMA; activations pair-interleaved float2 in smem.
// ---------------------------------------------------------------------------

#define NU   32
#define NX   128
#define NF   256
#define NIN  160           // NX + NU
#define NT   256           // timesteps
#define NB   1024          // batch
#define ROWS 8             // rows per CTA
#define NCTA (NB / ROWS)   // 128
#define NTHREADS 512

// Transposed weight scratch (static device memory: allowed, no allocation)
__device__ float g_W1T[NIN * NF];
__device__ float g_WlT[NIN * NX];
__device__ float g_W2T[NF * NF];
__device__ float g_W3T[NF * NX];
__device__ float g_Wo1T[NX * NF];
__device__ float g_Wo2T[NF * NF];
__device__ float g_Wo3T[NF * NX];

using ull = unsigned long long;

__device__ __forceinline__ ull pack2(float w) {
    ull r;
    asm("mov.b64 %0, {%1, %1};" : "=l"(r) : "f"(w));
    return r;
}
__device__ __forceinline__ void fma2(ull &d, ull a, ull b) {
    asm("fma.rn.f32x2 %0, %1, %2, %0;" : "+l"(d) : "l"(a), "l"(b));
}
__device__ __forceinline__ float2 u2f(ull v) {
    float2 r;
    asm("mov.b64 {%0, %1}, %2;" : "=f"(r.x), "=f"(r.y) : "l"(v));
    return r;
}

// 256-wide layer, split-K over 2 thread-halves. 512 threads participate.
// src: [4][K] float2 (pair-interleaved). dst/part: [4][256] float2.
// Two internal __syncthreads.
template <int K, bool RELU>
__device__ __forceinline__ void layerN256(const float* __restrict__ WT,   // [K][256]
                                          const float* __restrict__ bias, // [256]
                                          const float2* __restrict__ src,
                                          float2* __restrict__ dst,
                                          float2* __restrict__ part,
                                          int tid) {
    const int n = tid & 255;
    const int h = tid >> 8;           // 0 or 1
    const int k0 = h * (K / 2);
    ull a0 = 0, a1 = 0, a2 = 0, a3 = 0;
    const float* wp = WT + n;
#pragma unroll 4
    for (int kk = 0; kk < K / 2; kk += 2) {
        const int k = k0 + kk;
        ull w0 = pack2(__ldg(wp + (size_t)k * NF));
        ull w1 = pack2(__ldg(wp + (size_t)(k + 1) * NF));
        ulonglong2 z0 = *reinterpret_cast<const ulonglong2*>(src + 0 * K + k);
        ulonglong2 z1 = *reinterpret_cast<const ulonglong2*>(src + 1 * K + k);
        ulonglong2 z2 = *reinterpret_cast<const ulonglong2*>(src + 2 * K + k);
        ulonglong2 z3 = *reinterpret_cast<const ulonglong2*>(src + 3 * K + k);
        fma2(a0, z0.x, w0); fma2(a0, z0.y, w1);
        fma2(a1, z1.x, w0); fma2(a1, z1.y, w1);
        fma2(a2, z2.x, w0); fma2(a2, z2.y, w1);
        fma2(a3, z3.x, w0); fma2(a3, z3.y, w1);
    }
    if (h) {
        part[0 * NF + n] = u2f(a0); part[1 * NF + n] = u2f(a1);
        part[2 * NF + n] = u2f(a2); part[3 * NF + n] = u2f(a3);
    }
    __syncthreads();
    if (!h) {
        const float b = bias[n];
        ull accs[4] = {a0, a1, a2, a3};
#pragma unroll
        for (int p = 0; p < 4; ++p) {
            float2 v = u2f(accs[p]);
            float2 q = part[p * NF + n];
            v.x += q.x + b; v.y += q.y + b;
            if (RELU) { v.x = fmaxf(v.x, 0.f); v.y = fmaxf(v.y, 0.f); }
            dst[p * NF + n] = v;
        }
    }
    __syncthreads();
}

// 128-wide layer, split-K over 4 thread-quarters. 512 threads participate.
// part: [3][4][128] float2. Two internal __syncthreads.
template <int K>
__device__ __forceinline__ void layer128s(const float* __restrict__ WT,     // [K][NX]
                                          const float* __restrict__ bias,   // nullable
                                          const float2* __restrict__ src,   // [4][K]
                                          const float2* __restrict__ addsrc,// nullable [4][NX]
                                          float2* __restrict__ dst,         // [4][NX]
                                          float2* __restrict__ part,        // [3][4][NX]
                                          int tid) {
    const int n = tid & (NX - 1);
    const int q = tid >> 7;           // 0..3
    const int k0 = q * (K / 4);
    ull a0 = 0, a1 = 0, a2 = 0, a3 = 0;
    const float* wp = WT + n;
#pragma unroll 4
    for (int kk = 0; kk < K / 4; kk += 2) {
        const int k = k0 + kk;
        ull w0 = pack2(__ldg(wp + (size_t)k * NX));
        ull w1 = pack2(__ldg(wp + (size_t)(k + 1) * NX));
        ulonglong2 z0 = *reinterpret_cast<const ulonglong2*>(src + 0 * K + k);
        ulonglong2 z1 = *reinterpret_cast<const ulonglong2*>(src + 1 * K + k);
        ulonglong2 z2 = *reinterpret_cast<const ulonglong2*>(src + 2 * K + k);
        ulonglong2 z3 = *reinterpret_cast<const ulonglong2*>(src + 3 * K + k);
        fma2(a0, z0.x, w0); fma2(a0, z0.y, w1);
        fma2(a1, z1.x, w0); fma2(a1, z1.y, w1);
        fma2(a2, z2.x, w0); fma2(a2, z2.y, w1);
        fma2(a3, z3.x, w0); fma2(a3, z3.y, w1);
    }
    if (q) {
        float2* pp = part + (size_t)(q - 1) * 4 * NX;
        pp[0 * NX + n] = u2f(a0); pp[1 * NX + n] = u2f(a1);
        pp[2 * NX + n] = u2f(a2); pp[3 * NX + n] = u2f(a3);
    }
    __syncthreads();
    if (!q) {
        const float b = bias ? bias[n] : 0.f;
        ull accs[4] = {a0, a1, a2, a3};
#pragma unroll
        for (int p = 0; p < 4; ++p) {
            float2 v = u2f(accs[p]);
            float2 p0 = part[0 * 4 * NX + p * NX + n];
            float2 p1 = part[1 * 4 * NX + p * NX + n];
            float2 p2 = part[2 * 4 * NX + p * NX + n];
            v.x += p0.x + p1.x + p2.x + b;
            v.y += p0.y + p1.y + p2.y + b;
            if (addsrc) {
                float2 av = addsrc[p * NX + n];
                v.x += av.x; v.y += av.y;
            }
            dst[p * NX + n] = v;
        }
    }
    __syncthreads();
}

__global__ void prep_kernel(const float* __restrict__ W_lin, const float* __restrict__ W1,
                            const float* __restrict__ W2, const float* __restrict__ W3,
                            const float* __restrict__ Wo1, const float* __restrict__ Wo2,
                            const float* __restrict__ Wo3) {
    int i0 = blockIdx.x * blockDim.x + threadIdx.x;
    int stride = gridDim.x * blockDim.x;
    for (int j = i0; j < NF * NIN; j += stride) { int n = j / NIN, k = j % NIN; g_W1T[k * NF + n] = W1[j]; }
    for (int j = i0; j < NX * NIN; j += stride) { int m = j / NIN, k = j % NIN; g_WlT[k * NX + m] = W_lin[j]; }
    for (int j = i0; j < NF * NF;  j += stride) { int n = j / NF,  k = j % NF;  g_W2T[k * NF + n] = W2[j]; }
    for (int j = i0; j < NX * NF;  j += stride) { int m = j / NF,  k = j % NF;  g_W3T[k * NX + m] = W3[j]; }
    for (int j = i0; j < NF * NX;  j += stride) { int n = j / NX,  k = j % NX;  g_Wo1T[k * NF + n] = Wo1[j]; }
    for (int j = i0; j < NF * NF;  j += stride) { int n = j / NF,  k = j % NF;  g_Wo2T[k * NF + n] = Wo2[j]; }
    for (int j = i0; j < NX * NF;  j += stride) { int m = j / NF,  k = j % NF;  g_Wo3T[k * NX + m] = Wo3[j]; }
}

__global__ void __launch_bounds__(NTHREADS, 1)
ode_kernel(const float* __restrict__ input,   // [NT][NB][NU]
           const float* __restrict__ x0,      // [1][NB][NX]
           const float* __restrict__ dtp,     // scalar
           const float* __restrict__ b1, const float* __restrict__ b2,
           const float* __restrict__ b3, const float* __restrict__ bo1,
           const float* __restrict__ bo2, const float* __restrict__ bo3,
           float* __restrict__ y_out,         // [NT][NB][NX]
           float* __restrict__ xf_out)        // [NB][NX]
{
    __shared__ __align__(16) float2 s_ze[4 * NIN];  // z = [x | u]
    __shared__ __align__(16) float2 s_h1[4 * NF];
    __shared__ __align__(16) float2 s_h2[4 * NF];
    __shared__ __align__(16) float2 s_lin[4 * NX];
    __shared__ __align__(16) float2 s_k[4 * NX];
    __shared__ __align__(16) float2 s_ks[4 * NX];
    __shared__ __align__(16) float2 s_x[4 * NX];
    __shared__ __align__(16) float2 s_pN[4 * NF];       // partials for 256-wide layers
    __shared__ __align__(16) float2 s_p128[3 * 4 * NX]; // partials for 128-wide layers

    const int tid = threadIdx.x;
    const int rowbase = blockIdx.x * ROWS;
    const float dt = *dtp;
    const float dth = 0.5f * dt;
    const float dt6 = dt * (1.0f / 6.0f);

    // load x0 (pair-interleave rows)
    for (int idx = tid; idx < ROWS * NX; idx += NTHREADS) {
        int r = idx >> 7, c = idx & (NX - 1);
        float v = x0[(size_t)(rowbase + r) * NX + c];
        ((float*)&s_x[(r >> 1) * NX + c])[r & 1] = v;
    }
    __syncthreads();

    for (int t = 0; t < NT; ++t) {
        // u -> tail of z (cols 128..159); persists across the 4 RK4 evals
        if (tid < ROWS * NU) {
            int r = tid >> 5, c = tid & 31;
            float v = input[((size_t)t * NB + rowbase + r) * NU + c];
            ((float*)&s_ze[(r >> 1) * NIN + NX + c])[r & 1] = v;
        }
        // x -> head of z; zero ksum (4*NX = 512 elements = exactly 1 per thread)
        {
            int p = tid >> 7, c = tid & (NX - 1);
            s_ze[p * NIN + c] = s_x[tid];
            s_ks[tid] = make_float2(0.f, 0.f);
        }
        __syncthreads();

        // ---- RK4: 4 evaluations of dx_net ----
#pragma unroll 1
        for (int e = 0; e < 4; ++e) {
            layerN256<NIN, true>(g_W1T, b1, s_ze, s_h1, s_pN, tid);
            layer128s<NIN>(g_WlT, nullptr, s_ze, nullptr, s_lin, s_p128, tid);
            layerN256<NF, true>(g_W2T, b2, s_h1, s_h2, s_pN, tid);
            layer128s<NF>(g_W3T, b3, s_h2, s_lin, s_k, s_p128, tid); // k = lin + h2@W3T + b3

            const float we = (e == 1 || e == 2) ? 2.f : 1.f;
            const float ce = (e < 2) ? dth : dt;  // coef for next eval state
            {
                int idx = tid;
                float2 kv = s_k[idx];
                float2 s = s_ks[idx];
                s.x = fmaf(we, kv.x, s.x);
                s.y = fmaf(we, kv.y, s.y);
                s_ks[idx] = s;
                if (e < 3) {
                    int p = idx >> 7, c = idx & (NX - 1);
                    float2 xv = s_x[idx];
                    s_ze[p * NIN + c] = make_float2(fmaf(ce, kv.x, xv.x),
                                                    fmaf(ce, kv.y, xv.y));
                }
            }
            __syncthreads();
        }

        // x += dt/6 * (k1 + 2k2 + 2k3 + k4)
        {
            float2 xv = s_x[tid], s = s_ks[tid];
            xv.x = fmaf(dt6, s.x, xv.x);
            xv.y = fmaf(dt6, s.y, xv.y);
            s_x[tid] = xv;
        }
        __syncthreads();

        // ---- out_net(x_new) ----
        layerN256<NX, true>(g_Wo1T, bo1, s_x, s_h1, s_pN, tid);
        layerN256<NF, true>(g_Wo2T, bo2, s_h1, s_h2, s_pN, tid);
        layer128s<NF>(g_Wo3T, bo3, s_h2, nullptr, s_k, s_p128, tid); // y -> s_k

        // store y[t]
        for (int idx = tid; idx < ROWS * NX; idx += NTHREADS) {
            int r = idx >> 7, c = idx & (NX - 1);
            float v = ((const float*)&s_k[(r >> 1) * NX + c])[r & 1];
            y_out[((size_t)t * NB + rowbase + r) * NX + c] = v;
        }
        __syncthreads();
    }

    // store x_final
    for (int idx = tid; idx < ROWS * NX; idx += NTHREADS) {
        int r = idx >> 7, c = idx & (NX - 1);
        xf_out[(size_t)(rowbase + r) * NX + c] =
            ((const float*)&s_x[(r >> 1) * NX + c])[r & 1];
    }
}

extern "C" void kernel_launch(void* const* d_in, const int* in_sizes, int n_in,
                              void* d_out, int out_size) {
    const float* input = (const float*)d_in[0];
    const float* x_step = (const float*)d_in[1];
    const float* dtp   = (const float*)d_in[2];
    const float* W_lin = (const float*)d_in[3];
    const float* W1    = (const float*)d_in[4];
    const float* b1    = (const float*)d_in[5];
    const float* W2    = (const float*)d_in[6];
    const float* b2    = (const float*)d_in[7];
    const float* W3    = (const float*)d_in[8];
    const float* b3    = (const float*)d_in[9];
    const float* Wo1   = (const float*)d_in[10];
    const float* bo1   = (const float*)d_in[11];
    const float* Wo2   = (const float*)d_in[12];
    const float* bo2   = (const float*)d_in[13];
    const float* Wo3   = (const float*)d_in[14];
    const float* bo3   = (const float*)d_in[15];

    float* out = (float*)d_out;
    float* y_out  = out;                               // [NT][NB][NX]
    float* xf_out = out + (size_t)NT * NB * NX;        // [NB][NX]

    prep_kernel<<<256, 256>>>(W_lin, W1, W2, W3, Wo1, Wo2, Wo3);
    ode_kernel<<<NCTA, NTHREADS>>>(input, x_step, dtp,
                                   b1, b2, b3, bo1, bo2, bo3,
                                   y_out, xf_out);
}

// round 6
// speedup vs baseline: 1.6759x; 1.2631x over previous
#include <cuda_runtime.h>

// ---------------------------------------------------------------------------
// ODELayer: RK4 integration of a small MLP ODE, 256 steps, batch 1024.
// Rows independent -> 128 CTAs x 8 rows, no inter-CTA sync. 512 thr/CTA.
// Round 5: each thread computes 4 output columns (LDG.128 weights), so one
// 16B activation LDS feeds 4 fma2 -> L1 wavefronts drop below the fp32 FMA
// floor. Split-K 8-way (N=256) / 16-way (N=128) with radix-tree smem
// reduction in dynamic shared memory. fp32 packed f32x2 FMA throughout.
// ---------------------------------------------------------------------------

#define NU   32
#define NX   128
#define NF   256
#define NIN  160           // NX + NU
#define NT   256           // timesteps
#define NB   1024          // batch
#define ROWS 8             // rows per CTA
#define NCTA (NB / ROWS)   // 128
#define NTHREADS 512

// dyn smem: activations (4736 float2) + partials (7680 float2)
#define SMEM_F2  (4*NIN + 4*NF + 4*NF + 4*NX + 4*NX + 4*NX + 4*NX + 7680)
#define SMEM_BYTES (SMEM_F2 * 8)

// Transposed weight scratch (static device memory: allowed, no allocation)
__device__ float g_W1T[NIN * NF];
__device__ float g_WlT[NIN * NX];
__device__ float g_W2T[NF * NF];
__device__ float g_W3T[NF * NX];
__device__ float g_Wo1T[NX * NF];
__device__ float g_Wo2T[NF * NF];
__device__ float g_Wo3T[NF * NX];

using ull = unsigned long long;

__device__ __forceinline__ ull pack2(float w) {
    ull r;
    asm("mov.b64 %0, {%1, %1};" : "=l"(r) : "f"(w));
    return r;
}
__device__ __forceinline__ void fma2(ull &d, ull a, ull b) {
    asm("fma.rn.f32x2 %0, %1, %2, %0;" : "+l"(d) : "l"(a), "l"(b));
}
__device__ __forceinline__ void addf2(ull &d, ull a) {
    asm("add.rn.f32x2 %0, %0, %1;" : "+l"(d) : "l"(a));
}
__device__ __forceinline__ float2 u2f(ull v) {
    float2 r;
    asm("mov.b64 {%0, %1}, %2;" : "=f"(r.x), "=f"(r.y) : "l"(v));
    return r;
}

// store this thread's 16 accumulators (4 pairs x 4 cols) into partial set pp
template <int N>
__device__ __forceinline__ void store_part(float2* pp, const ull* acc, int n0) {
#pragma unroll
    for (int p = 0; p < 4; ++p) {
        float2 a = u2f(acc[p*4+0]), b = u2f(acc[p*4+1]);
        float2 c = u2f(acc[p*4+2]), d = u2f(acc[p*4+3]);
        float4* q = reinterpret_cast<float4*>(pp + (size_t)p * N + n0);
        q[0] = make_float4(a.x, a.y, b.x, b.y);
        q[1] = make_float4(c.x, c.y, d.x, d.y);
    }
}
template <int N>
__device__ __forceinline__ void add_part(const float2* pp, ull* acc, int n0) {
#pragma unroll
    for (int p = 0; p < 4; ++p) {
        ulonglong2 q0 = *reinterpret_cast<const ulonglong2*>(pp + (size_t)p * N + n0);
        ulonglong2 q1 = *reinterpret_cast<const ulonglong2*>(pp + (size_t)p * N + n0 + 2);
        addf2(acc[p*4+0], q0.x); addf2(acc[p*4+1], q0.y);
        addf2(acc[p*4+2], q1.x); addf2(acc[p*4+3], q1.y);
    }
}

// Unified layer: N output columns, each thread owns 4 columns for all 8 rows.
// G = N/4 column-groups, S = 512/G k-groups (8 for N=256, 16 for N=128).
// src: [4][K] float2 pair-interleaved. dst: [4][N]. part: scratch.
// Ends with a trailing __syncthreads (all 512 threads must call).
template <int K, int N, bool RELU>
__device__ __forceinline__ void layer4(const float* __restrict__ WT,     // [K][N]
                                       const float* __restrict__ bias,   // nullable
                                       const float2* __restrict__ src,
                                       const float2* __restrict__ addsrc,// nullable [4][N]
                                       float2* __restrict__ dst,
                                       float2* __restrict__ part,
                                       int tid) {
    constexpr int G  = N / 4;
    constexpr int S  = NTHREADS / G;   // 8 or 16
    constexpr int KS = K / S;          // even for all our shapes
    const int cg = tid & (G - 1);
    const int kg = tid / G;
    const int n0 = cg * 4;

    ull acc[16];
#pragma unroll
    for (int i = 0; i < 16; ++i) acc[i] = 0;

    const float* wp = WT + n0;
    const int kbase = kg * KS;
#pragma unroll 2
    for (int kk = 0; kk < KS; kk += 2) {
        const int k = kbase + kk;
        float4 wa = __ldg(reinterpret_cast<const float4*>(wp + (size_t)k * N));
        float4 wb = __ldg(reinterpret_cast<const float4*>(wp + (size_t)(k + 1) * N));
        ull wa0 = pack2(wa.x), wa1 = pack2(wa.y), wa2 = pack2(wa.z), wa3 = pack2(wa.w);
        ull wb0 = pack2(wb.x), wb1 = pack2(wb.y), wb2 = pack2(wb.z), wb3 = pack2(wb.w);
#pragma unroll
        for (int p = 0; p < 4; ++p) {
            ulonglong2 z = *reinterpret_cast<const ulonglong2*>(src + (size_t)p * K + k);
            fma2(acc[p*4+0], z.x, wa0); fma2(acc[p*4+0], z.y, wb0);
            fma2(acc[p*4+1], z.x, wa1); fma2(acc[p*4+1], z.y, wb1);
            fma2(acc[p*4+2], z.x, wa2); fma2(acc[p*4+2], z.y, wb2);
            fma2(acc[p*4+3], z.x, wa3); fma2(acc[p*4+3], z.y, wb3);
        }
    }

    // ---- split-K reduction ----
    constexpr size_t SET = (size_t)4 * N;  // float2 per partial set
    if (S == 8) {
        if (kg >= 1) store_part<N>(part + (size_t)(kg - 1) * SET, acc, n0);
        __syncthreads();
        if (kg == 0) {
#pragma unroll
            for (int s = 0; s < 7; ++s) add_part<N>(part + (size_t)s * SET, acc, n0);
        }
    } else { // S == 16: two radix-4 levels
        if (kg >= 4) store_part<N>(part + (size_t)(kg - 4) * SET, acc, n0);
        __syncthreads();
        if (kg < 4) {
            add_part<N>(part + (size_t)(kg + 0) * SET, acc, n0);
            add_part<N>(part + (size_t)(kg + 4) * SET, acc, n0);
            add_part<N>(part + (size_t)(kg + 8) * SET, acc, n0);
        }
        if (kg >= 1 && kg < 4) store_part<N>(part + (size_t)(12 + kg - 1) * SET, acc, n0);
        __syncthreads();
        if (kg == 0) {
            add_part<N>(part + (size_t)12 * SET, acc, n0);
            add_part<N>(part + (size_t)13 * SET, acc, n0);
            add_part<N>(part + (size_t)14 * SET, acc, n0);
        }
    }

    // ---- finalize: bias, residual add, relu, store ----
    if (kg == 0) {
        float4 bv = make_float4(0.f, 0.f, 0.f, 0.f);
        if (bias) bv = __ldg(reinterpret_cast<const float4*>(bias + n0));
#pragma unroll
        for (int p = 0; p < 4; ++p) {
            float2 v0 = u2f(acc[p*4+0]), v1 = u2f(acc[p*4+1]);
            float2 v2 = u2f(acc[p*4+2]), v3 = u2f(acc[p*4+3]);
            v0.x += bv.x; v0.y += bv.x;
            v1.x += bv.y; v1.y += bv.y;
            v2.x += bv.z; v2.y += bv.z;
            v3.x += bv.w; v3.y += bv.w;
            if (addsrc) {
                const float2* ap = addsrc + (size_t)p * N + n0;
                float2 a0 = ap[0], a1 = ap[1], a2 = ap[2], a3 = ap[3];
                v0.x += a0.x; v0.y += a0.y; v1.x += a1.x; v1.y += a1.y;
                v2.x += a2.x; v2.y += a2.y; v3.x += a3.x; v3.y += a3.y;
            }
            if (RELU) {
                v0.x = fmaxf(v0.x, 0.f); v0.y = fmaxf(v0.y, 0.f);
                v1.x = fmaxf(v1.x, 0.f); v1.y = fmaxf(v1.y, 0.f);
                v2.x = fmaxf(v2.x, 0.f); v2.y = fmaxf(v2.y, 0.f);
                v3.x = fmaxf(v3.x, 0.f); v3.y = fmaxf(v3.y, 0.f);
            }
            float4* q = reinterpret_cast<float4*>(dst + (size_t)p * N + n0);
            q[0] = make_float4(v0.x, v0.y, v1.x, v1.y);
            q[1] = make_float4(v2.x, v2.y, v3.x, v3.y);
        }
    }
    __syncthreads();
}

__global__ void prep_kernel(const float* __restrict__ W_lin, const float* __restrict__ W1,
                            const float* __restrict__ W2, const float* __restrict__ W3,
                            const float* __restrict__ Wo1, const float* __restrict__ Wo2,
                            const float* __restrict__ Wo3) {
    int i0 = blockIdx.x * blockDim.x + threadIdx.x;
    int stride = gridDim.x * blockDim.x;
    for (int j = i0; j < NF * NIN; j += stride) { int n = j / NIN, k = j % NIN; g_W1T[k * NF + n] = W1[j]; }
    for (int j = i0; j < NX * NIN; j += stride) { int m = j / NIN, k = j % NIN; g_WlT[k * NX + m] = W_lin[j]; }
    for (int j = i0; j < NF * NF;  j += stride) { int n = j / NF,  k = j % NF;  g_W2T[k * NF + n] = W2[j]; }
    for (int j = i0; j < NX * NF;  j += stride) { int m = j / NF,  k = j % NF;  g_W3T[k * NX + m] = W3[j]; }
    for (int j = i0; j < NF * NX;  j += stride) { int n = j / NX,  k = j % NX;  g_Wo1T[k * NF + n] = Wo1[j]; }
    for (int j = i0; j < NF * NF;  j += stride) { int n = j / NF,  k = j % NF;  g_Wo2T[k * NF + n] = Wo2[j]; }
    for (int j = i0; j < NF * NX;  j += stride) { int m = j / NF,  k = j % NF;  g_Wo3T[k * NX + m] = Wo3[j]; }
}

__global__ void __launch_bounds__(NTHREADS, 1)
ode_kernel(const float* __restrict__ input,   // [NT][NB][NU]
           const float* __restrict__ x0,      // [1][NB][NX]
           const float* __restrict__ dtp,     // scalar
           const float* __restrict__ b1, const float* __restrict__ b2,
           const float* __restrict__ b3, const float* __restrict__ bo1,
           const float* __restrict__ bo2, const float* __restrict__ bo3,
           float* __restrict__ y_out,         // [NT][NB][NX]
           float* __restrict__ xf_out)        // [NB][NX]
{
    extern __shared__ __align__(16) char smem_raw[];
    float2* s_ze   = reinterpret_cast<float2*>(smem_raw);   // [4][NIN]
    float2* s_h1   = s_ze  + 4 * NIN;                       // [4][NF]
    float2* s_h2   = s_h1  + 4 * NF;                        // [4][NF]
    float2* s_lin  = s_h2  + 4 * NF;                        // [4][NX]
    float2* s_k    = s_lin + 4 * NX;                        // [4][NX]
    float2* s_ks   = s_k   + 4 * NX;                        // [4][NX]
    float2* s_x    = s_ks  + 4 * NX;                        // [4][NX]
    float2* s_part = s_x   + 4 * NX;                        // 7680 float2

    const int tid = threadIdx.x;
    const int rowbase = blockIdx.x * ROWS;
    const float dt = *dtp;
    const float dth = 0.5f * dt;
    const float dt6 = dt * (1.0f / 6.0f);

    // load x0 (pair-interleave rows)
    for (int idx = tid; idx < ROWS * NX; idx += NTHREADS) {
        int r = idx >> 7, c = idx & (NX - 1);
        float v = x0[(size_t)(rowbase + r) * NX + c];
        ((float*)&s_x[(r >> 1) * NX + c])[r & 1] = v;
    }
    __syncthreads();

    for (int t = 0; t < NT; ++t) {
        // u -> tail of z (cols 128..159); persists across the 4 RK4 evals
        if (tid < ROWS * NU) {
            int r = tid >> 5, c = tid & 31;
            float v = input[((size_t)t * NB + rowbase + r) * NU + c];
            ((float*)&s_ze[(r >> 1) * NIN + NX + c])[r & 1] = v;
        }
        // x -> head of z; zero ksum (4*NX = 512 elements = 1 per thread)
        {
            int p = tid >> 7, c = tid & (NX - 1);
            s_ze[p * NIN + c] = s_x[tid];
            s_ks[tid] = make_float2(0.f, 0.f);
        }
        __syncthreads();

        // ---- RK4: 4 evaluations of dx_net ----
#pragma unroll 1
        for (int e = 0; e < 4; ++e) {
            layer4<NIN, NF, true >(g_W1T, b1, s_ze, nullptr, s_h1, s_part, tid);
            layer4<NIN, NX, false>(g_WlT, nullptr, s_ze, nullptr, s_lin, s_part, tid);
            layer4<NF,  NF, true >(g_W2T, b2, s_h1, nullptr, s_h2, s_part, tid);
            layer4<NF,  NX, false>(g_W3T, b3, s_h2, s_lin, s_k, s_part, tid); // k = lin + h2@W3T + b3

            const float we = (e == 1 || e == 2) ? 2.f : 1.f;
            const float ce = (e < 2) ? dth : dt;  // coef for next eval state
            {
                float2 kv = s_k[tid];
                float2 s = s_ks[tid];
                s.x = fmaf(we, kv.x, s.x);
                s.y = fmaf(we, kv.y, s.y);
                s_ks[tid] = s;
                if (e < 3) {
                    int p = tid >> 7, c = tid & (NX - 1);
                    float2 xv = s_x[tid];
                    s_ze[p * NIN + c] = make_float2(fmaf(ce, kv.x, xv.x),
                                                    fmaf(ce, kv.y, xv.y));
                }
            }
            __syncthreads();
        }

        // x += dt/6 * (k1 + 2k2 + 2k3 + k4)
        {
            float2 xv = s_x[tid], s = s_ks[tid];
            xv.x = fmaf(dt6, s.x, xv.x);
            xv.y = fmaf(dt6, s.y, xv.y);
            s_x[tid] = xv;
        }
        __syncthreads();

        // ---- out_net(x_new) ----
        layer4<NX, NF, true >(g_Wo1T, bo1, s_x, nullptr, s_h1, s_part, tid);
        layer4<NF, NF, true >(g_Wo2T, bo2, s_h1, nullptr, s_h2, s_part, tid);
        layer4<NF, NX, false>(g_Wo3T, bo3, s_h2, nullptr, s_k, s_part, tid); // y -> s_k

        // store y[t]
        for (int idx = tid; idx < ROWS * NX; idx += NTHREADS) {
            int r = idx >> 7, c = idx & (NX - 1);
            float v = ((const float*)&s_k[(r >> 1) * NX + c])[r & 1];
            y_out[((size_t)t * NB + rowbase + r) * NX + c] = v;
        }
        __syncthreads();
    }

    // store x_final
    for (int idx = tid; idx < ROWS * NX; idx += NTHREADS) {
        int r = idx >> 7, c = idx & (NX - 1);
        xf_out[(size_t)(rowbase + r) * NX + c] =
            ((const float*)&s_x[(r >> 1) * NX + c])[r & 1];
    }
}

extern "C" void kernel_launch(void* const* d_in, const int* in_sizes, int n_in,
                              void* d_out, int out_size) {
    const float* input = (const float*)d_in[0];
    const float* x_step = (const float*)d_in[1];
    const float* dtp   = (const float*)d_in[2];
    const float* W_lin = (const float*)d_in[3];
    const float* W1    = (const float*)d_in[4];
    const float* b1    = (const float*)d_in[5];
    const float* W2    = (const float*)d_in[6];
    const float* b2    = (const float*)d_in[7];
    const float* W3    = (const float*)d_in[8];
    const float* b3    = (const float*)d_in[9];
    const float* Wo1   = (const float*)d_in[10];
    const float* bo1   = (const float*)d_in[11];
    const float* Wo2   = (const float*)d_in[12];
    const float* bo2   = (const float*)d_in[13];
    const float* Wo3   = (const float*)d_in[14];
    const float* bo3   = (const float*)d_in[15];

    float* out = (float*)d_out;
    float* y_out  = out;                               // [NT][NB][NX]
    float* xf_out = out + (size_t)NT * NB * NX;        // [NB][NX]

    static bool attr_done = false;
    if (!attr_done) {
        cudaFuncSetAttribute(ode_kernel,
                             cudaFuncAttributeMaxDynamicSharedMemorySize,
                             SMEM_BYTES);
        attr_done = true;
    }

    prep_kernel<<<256, 256>>>(W_lin, W1, W2, W3, Wo1, Wo2, Wo3);
    ode_kernel<<<NCTA, NTHREADS, SMEM_BYTES>>>(input, x_step, dtp,
                                               b1, b2, b3, bo1, bo2, bo3,
                                               y_out, xf_out);
}

// round 8
// speedup vs baseline: 1.9889x; 1.1868x over previous
#include <cuda_runtime.h>

// ---------------------------------------------------------------------------
// ODELayer: RK4 integration of a small MLP ODE, 256 steps, batch 1024.
// Round 7:
//  Phase 1 (scan): dx_net only (out_net removed from the loop). 128 CTAs x
//    8 rows, 512 thr. Split-K layers with ALL-THREAD parallel reduction
//    (no kg==0 serial tail). x history stored to 128MiB __device__ scratch.
//  Phase 2: out_net over all 256*1024 rows as a big-M batched MLP:
//    64 rows/CTA, full-K per thread (no reduction), weight reuse over 4
//    row-pairs. 4096 CTAs, fma-bound.
// fp32 packed f32x2 FMA throughout.
// ---------------------------------------------------------------------------

#define NU   32
#define NX   128
#define NF   256
#define NIN  160           // NX + NU
#define NT   256           // timesteps
#define NB   1024          // batch
#define ROWS 8             // rows per CTA (phase 1)
#define NCTA (NB / ROWS)   // 128
#define NTHREADS 512

// phase 2 tiling
#define M2   64                    // rows per CTA
#define P2   (M2 / 2)              // 32 pairs
#define NCTA2 ((NT * NB) / M2)     // 4096

// phase1 dyn smem (float2 units): ze 640 + h1 1024 + h2 1024 + lin 512 +
// k 512 + ks 512 + x 512 + part 8192  = 12928
#define SMEM1_F2   (4*NIN + 4*NF + 4*NF + 4*NX + 4*NX + 4*NX + 4*NX + 8192)
#define SMEM1_BYTES (SMEM1_F2 * 8)
// phase2 dyn smem: x 4096 + h1 8192 + h2 8192 = 20480 f2 = 160KB
#define SMEM2_F2   (P2*NX + P2*NF + P2*NF)
#define SMEM2_BYTES (SMEM2_F2 * 8)

// x-history scratch: [NT][NB][NX] floats = 128 MiB (static device mem: allowed)
__device__ float g_xhist[(size_t)NT * NB * NX];

// Transposed weight scratch
__device__ float g_W1T[NIN * NF];
__device__ float g_WlT[NIN * NX];
__device__ float g_W2T[NF * NF];
__device__ float g_W3T[NF * NX];
__device__ float g_Wo1T[NX * NF];
__device__ float g_Wo2T[NF * NF];
__device__ float g_Wo3T[NF * NX];

using ull = unsigned long long;

__device__ __forceinline__ ull pack2(float w) {
    ull r;
    asm("mov.b64 %0, {%1, %1};" : "=l"(r) : "f"(w));
    return r;
}
__device__ __forceinline__ void fma2(ull &d, ull a, ull b) {
    asm("fma.rn.f32x2 %0, %1, %2, %0;" : "+l"(d) : "l"(a), "l"(b));
}
__device__ __forceinline__ void addf2(ull &d, ull a) {
    asm("add.rn.f32x2 %0, %0, %1;" : "+l"(d) : "l"(a));
}
__device__ __forceinline__ float2 u2f(ull v) {
    float2 r;
    asm("mov.b64 {%0, %1}, %2;" : "=f"(r.x), "=f"(r.y) : "l"(v));
    return r;
}

// ---------------------------------------------------------------------------
// Phase-1 layer: N outputs, each thread computes 4 cols x 4 row-pairs over a
// K/S slice; partials stored by ALL S groups; reduction + bias/relu/residual
// done cooperatively by all 512 threads on disjoint chunks.
// src: [4][K] f2 (pair-interleaved). dst: [4][N] f2. part: [S][4][N] f2.
// Two internal __syncthreads (all 512 threads must call).
// ---------------------------------------------------------------------------
template <int K, int N, bool RELU>
__device__ __forceinline__ void layer_ps(const float* __restrict__ WT,     // [K][N]
                                         const float* __restrict__ bias,   // nullable
                                         const float2* __restrict__ src,
                                         const float2* __restrict__ addsrc,// nullable [4][N]
                                         float2* __restrict__ dst,
                                         float2* __restrict__ part,
                                         int tid) {
    constexpr int G  = N / 4;          // 64 or 32
    constexpr int S  = NTHREADS / G;   // 8 or 16
    constexpr int KS = K / S;
    const int cg = tid & (G - 1);
    const int kg = tid / G;
    const int n0 = cg * 4;

    ull acc[16];
#pragma unroll
    for (int i = 0; i < 16; ++i) acc[i] = 0;

    const float* wp = WT + n0;
    const int kbase = kg * KS;
#pragma unroll 2
    for (int kk = 0; kk < KS; kk += 2) {
        const int k = kbase + kk;
        float4 wa = __ldg(reinterpret_cast<const float4*>(wp + (size_t)k * N));
        float4 wb = __ldg(reinterpret_cast<const float4*>(wp + (size_t)(k + 1) * N));
        ull wa0 = pack2(wa.x), wa1 = pack2(wa.y), wa2 = pack2(wa.z), wa3 = pack2(wa.w);
        ull wb0 = pack2(wb.x), wb1 = pack2(wb.y), wb2 = pack2(wb.z), wb3 = pack2(wb.w);
#pragma unroll
        for (int p = 0; p < 4; ++p) {
            ulonglong2 z = *reinterpret_cast<const ulonglong2*>(src + (size_t)p * K + k);
            fma2(acc[p*4+0], z.x, wa0); fma2(acc[p*4+0], z.y, wb0);
            fma2(acc[p*4+1], z.x, wa1); fma2(acc[p*4+1], z.y, wb1);
            fma2(acc[p*4+2], z.x, wa2); fma2(acc[p*4+2], z.y, wb2);
            fma2(acc[p*4+3], z.x, wa3); fma2(acc[p*4+3], z.y, wb3);
        }
    }

    // store partials (all S groups)
    {
        float2* pp = part + (size_t)kg * (4 * N);
#pragma unroll
        for (int p = 0; p < 4; ++p) {
            float2 a = u2f(acc[p*4+0]), b = u2f(acc[p*4+1]);
            float2 c = u2f(acc[p*4+2]), d = u2f(acc[p*4+3]);
            float4* q = reinterpret_cast<float4*>(pp + (size_t)p * N + n0);
            q[0] = make_float4(a.x, a.y, b.x, b.y);
            q[1] = make_float4(c.x, c.y, d.x, d.y);
        }
    }
    __syncthreads();

    // cooperative reduction over S sets; each thread owns 4N/512 f2 of output
    if constexpr (N == 256) {
        const int j = 2 * tid;                // two f2 (16B) per thread
        ull a0 = 0, a1 = 0;
#pragma unroll
        for (int s = 0; s < S; ++s) {
            ulonglong2 q = *reinterpret_cast<const ulonglong2*>(part + (size_t)s * (4 * N) + j);
            addf2(a0, q.x); addf2(a1, q.y);
        }
        const int col = j & (N - 1);
        float2 v0 = u2f(a0), v1 = u2f(a1);
        float b0 = bias ? bias[col]     : 0.f;
        float b1 = bias ? bias[col + 1] : 0.f;
        v0.x += b0; v0.y += b0;
        v1.x += b1; v1.y += b1;
        if (addsrc) {
            float2 q0 = addsrc[j], q1 = addsrc[j + 1];
            v0.x += q0.x; v0.y += q0.y; v1.x += q1.x; v1.y += q1.y;
        }
        if (RELU) {
            v0.x = fmaxf(v0.x, 0.f); v0.y = fmaxf(v0.y, 0.f);
            v1.x = fmaxf(v1.x, 0.f); v1.y = fmaxf(v1.y, 0.f);
        }
        *reinterpret_cast<float4*>(dst + j) = make_float4(v0.x, v0.y, v1.x, v1.y);
    } else {                                   // N == 128: one f2 per thread
        const int j = tid;
        ull a0 = 0;
#pragma unroll
        for (int s = 0; s < S; ++s)
            addf2(a0, *reinterpret_cast<const ull*>(part + (size_t)s * (4 * N) + j));
        const int col = j & (N - 1);
        float2 v0 = u2f(a0);
        float b0 = bias ? bias[col] : 0.f;
        v0.x += b0; v0.y += b0;
        if (addsrc) { float2 q0 = addsrc[j]; v0.x += q0.x; v0.y += q0.y; }
        if (RELU) { v0.x = fmaxf(v0.x, 0.f); v0.y = fmaxf(v0.y, 0.f); }
        dst[j] = v0;
    }
    __syncthreads();
}

// ---------------------------------------------------------------------------
// Phase-2 layer: full-K per thread (no reduction). Thread owns 4 cols x PPT
// row-pairs. src: [P2][K] f2, dst: [P2][N] f2. No internal sync.
// ---------------------------------------------------------------------------
template <int K, int N, bool RELU, int PPT>
__device__ __forceinline__ void layer_full(const float* __restrict__ WT,   // [K][N]
                                           const float* __restrict__ bias, // [N]
                                           const float2* __restrict__ src,
                                           float2* __restrict__ dst,
                                           int tid) {
    constexpr int G = N / 4;
    const int cg = tid & (G - 1);
    const int pg = tid / G;
    const int p0 = pg * PPT;
    const int n0 = cg * 4;

    ull acc[PPT * 4];
#pragma unroll
    for (int i = 0; i < PPT * 4; ++i) acc[i] = 0;

    const float* wp = WT + n0;
#pragma unroll 2
    for (int k = 0; k < K; k += 2) {
        float4 wa = __ldg(reinterpret_cast<const float4*>(wp + (size_t)k * N));
        float4 wb = __ldg(reinterpret_cast<const float4*>(wp + (size_t)(k + 1) * N));
        ull wa0 = pack2(wa.x), wa1 = pack2(wa.y), wa2 = pack2(wa.z), wa3 = pack2(wa.w);
        ull wb0 = pack2(wb.x), wb1 = pack2(wb.y), wb2 = pack2(wb.z), wb3 = pack2(wb.w);
#pragma unroll
        for (int p = 0; p < PPT; ++p) {
            ulonglong2 z = *reinterpret_cast<const ulonglong2*>(src + (size_t)(p0 + p) * K + k);
            fma2(acc[p*4+0], z.x, wa0); fma2(acc[p*4+0], z.y, wb0);
            fma2(acc[p*4+1], z.x, wa1); fma2(acc[p*4+1], z.y, wb1);
            fma2(acc[p*4+2], z.x, wa2); fma2(acc[p*4+2], z.y, wb2);
            fma2(acc[p*4+3], z.x, wa3); fma2(acc[p*4+3], z.y, wb3);
        }
    }

    float4 bv = __ldg(reinterpret_cast<const float4*>(bias + n0));
#pragma unroll
    for (int p = 0; p < PPT; ++p) {
        float2 v0 = u2f(acc[p*4+0]), v1 = u2f(acc[p*4+1]);
        float2 v2 = u2f(acc[p*4+2]), v3 = u2f(acc[p*4+3]);
        v0.x += bv.x; v0.y += bv.x;
        v1.x += bv.y; v1.y += bv.y;
        v2.x += bv.z; v2.y += bv.z;
        v3.x += bv.w; v3.y += bv.w;
        if (RELU) {
            v0.x = fmaxf(v0.x, 0.f); v0.y = fmaxf(v0.y, 0.f);
            v1.x = fmaxf(v1.x, 0.f); v1.y = fmaxf(v1.y, 0.f);
            v2.x = fmaxf(v2.x, 0.f); v2.y = fmaxf(v2.y, 0.f);
            v3.x = fmaxf(v3.x, 0.f); v3.y = fmaxf(v3.y, 0.f);
        }
        float4* q = reinterpret_cast<float4*>(dst + (size_t)(p0 + p) * N + n0);
        q[0] = make_float4(v0.x, v0.y, v1.x, v1.y);
        q[1] = make_float4(v2.x, v2.y, v3.x, v3.y);
    }
}

__global__ void prep_kernel(const float* __restrict__ W_lin, const float* __restrict__ W1,
                            const float* __restrict__ W2, const float* __restrict__ W3,
                            const float* __restrict__ Wo1, const float* __restrict__ Wo2,
                            const float* __restrict__ Wo3) {
    int i0 = blockIdx.x * blockDim.x + threadIdx.x;
    int stride = gridDim.x * blockDim.x;
    for (int j = i0; j < NF * NIN; j += stride) { int n = j / NIN, k = j % NIN; g_W1T[k * NF + n] = W1[j]; }
    for (int j = i0; j < NX * NIN; j += stride) { int m = j / NIN, k = j % NIN; g_WlT[k * NX + m] = W_lin[j]; }
    for (int j = i0; j < NF * NF;  j += stride) { int n = j / NF,  k = j % NF;  g_W2T[k * NF + n] = W2[j]; }
    for (int j = i0; j < NX * NF;  j += stride) { int m = j / NF,  k = j % NF;  g_W3T[k * NX + m] = W3[j]; }
    for (int j = i0; j < NF * NX;  j += stride) { int n = j / NX,  k = j % NX;  g_Wo1T[k * NF + n] = Wo1[j]; }
    for (int j = i0; j < NF * NF;  j += stride) { int n = j / NF,  k = j % NF;  g_Wo2T[k * NF + n] = Wo2[j]; }
    for (int j = i0; j < NF * NX;  j += stride) { int m = j / NF,  k = j % NF;  g_Wo3T[k * NX + m] = Wo3[j]; }
}

// ---------------------------------------------------------------------------
// Phase 1: RK4 scan, dx_net only. Stores x_{t+1} history to g_xhist.
// ---------------------------------------------------------------------------
__global__ void __launch_bounds__(NTHREADS, 1)
ode_kernel(const float* __restrict__ input,   // [NT][NB][NU]
           const float* __restrict__ x0,      // [1][NB][NX]
           const float* __restrict__ dtp,     // scalar
           const float* __restrict__ b1, const float* __restrict__ b2,
           const float* __restrict__ b3,
           float* __restrict__ xf_out)        // [NB][NX]
{
    extern __shared__ __align__(16) char smem_raw[];
    float2* s_ze   = reinterpret_cast<float2*>(smem_raw);   // [4][NIN]
    float2* s_h1   = s_ze  + 4 * NIN;                       // [4][NF]
    float2* s_h2   = s_h1  + 4 * NF;                        // [4][NF]
    float2* s_lin  = s_h2  + 4 * NF;                        // [4][NX]
    float2* s_k    = s_lin + 4 * NX;                        // [4][NX]
    float2* s_ks   = s_k   + 4 * NX;                        // [4][NX]
    float2* s_x    = s_ks  + 4 * NX;                        // [4][NX]
    float2* s_part = s_x   + 4 * NX;                        // 8192 f2

    const int tid = threadIdx.x;
    const int rowbase = blockIdx.x * ROWS;
    const float dt = *dtp;
    const float dth = 0.5f * dt;
    const float dt6 = dt * (1.0f / 6.0f);

    // load x0 (pair-interleave rows)
    for (int idx = tid; idx < ROWS * NX; idx += NTHREADS) {
        int r = idx >> 7, c = idx & (NX - 1);
        float v = x0[(size_t)(rowbase + r) * NX + c];
        ((float*)&s_x[(r >> 1) * NX + c])[r & 1] = v;
    }
    __syncthreads();

    for (int t = 0; t < NT; ++t) {
        // u -> tail of z; x -> head of z; zero ksum
        if (tid < ROWS * NU) {
            int r = tid >> 5, c = tid & 31;
            float v = input[((size_t)t * NB + rowbase + r) * NU + c];
            ((float*)&s_ze[(r >> 1) * NIN + NX + c])[r & 1] = v;
        }
        {
            int p = tid >> 7, c = tid & (NX - 1);
            s_ze[p * NIN + c] = s_x[tid];
            s_ks[tid] = make_float2(0.f, 0.f);
        }
        __syncthreads();

        // ---- RK4: 4 evaluations of dx_net ----
#pragma unroll 1
        for (int e = 0; e < 4; ++e) {
            layer_ps<NIN, NF, true >(g_W1T, b1, s_ze, nullptr, s_h1, s_part, tid);
            layer_ps<NIN, NX, false>(g_WlT, nullptr, s_ze, nullptr, s_lin, s_part, tid);
            layer_ps<NF,  NF, true >(g_W2T, b2, s_h1, nullptr, s_h2, s_part, tid);
            layer_ps<NF,  NX, false>(g_W3T, b3, s_h2, s_lin, s_k, s_part, tid);

            const float we = (e == 1 || e == 2) ? 2.f : 1.f;
            const float ce = (e < 2) ? dth : dt;
            {
                float2 kv = s_k[tid];
                float2 s = s_ks[tid];
                s.x = fmaf(we, kv.x, s.x);
                s.y = fmaf(we, kv.y, s.y);
                s_ks[tid] = s;
                if (e < 3) {
                    int p = tid >> 7, c = tid & (NX - 1);
                    float2 xv = s_x[tid];
                    s_ze[p * NIN + c] = make_float2(fmaf(ce, kv.x, xv.x),
                                                    fmaf(ce, kv.y, xv.y));
                }
            }
            __syncthreads();
        }

        // x += dt/6 * (k1 + 2k2 + 2k3 + k4)
        {
            float2 xv = s_x[tid], s = s_ks[tid];
            xv.x = fmaf(dt6, s.x, xv.x);
            xv.y = fmaf(dt6, s.y, xv.y);
            s_x[tid] = xv;
        }
        __syncthreads();

        // store x_{t+1} history (coalesced)
        for (int idx = tid; idx < ROWS * NX; idx += NTHREADS) {
            int r = idx >> 7, c = idx & (NX - 1);
            float v = ((const float*)&s_x[(r >> 1) * NX + c])[r & 1];
            g_xhist[((size_t)t * NB + rowbase + r) * NX + c] = v;
        }
        // no extra sync needed: next iteration writes s_ze/s_ks only, reads s_x
        __syncthreads();
    }

    // store x_final
    for (int idx = tid; idx < ROWS * NX; idx += NTHREADS) {
        int r = idx >> 7, c = idx & (NX - 1);
        xf_out[(size_t)(rowbase + r) * NX + c] =
            ((const float*)&s_x[(r >> 1) * NX + c])[r & 1];
    }
}

// ---------------------------------------------------------------------------
// Phase 2: out_net over all NT*NB rows, 64 rows per CTA.
// ---------------------------------------------------------------------------
__global__ void __launch_bounds__(NTHREADS, 1)
out_kernel(const float* __restrict__ bo1, const float* __restrict__ bo2,
           const float* __restrict__ bo3,
           float* __restrict__ y_out)         // [NT*NB][NX]
{
    extern __shared__ __align__(16) char smem_raw[];
    float2* s_x  = reinterpret_cast<float2*>(smem_raw);  // [P2][NX]
    float2* s_h1 = s_x  + P2 * NX;                       // [P2][NF]
    float2* s_h2 = s_h1 + P2 * NF;                       // [P2][NF]

    const int tid = threadIdx.x;
    const size_t R0 = (size_t)blockIdx.x * M2;

    // load x tile (pair-interleaved)
    for (int idx = tid; idx < M2 * NX; idx += NTHREADS) {
        int r = idx >> 7, c = idx & (NX - 1);
        float v = g_xhist[(R0 + r) * NX + c];
        ((float*)&s_x[(r >> 1) * NX + c])[r & 1] = v;
    }
    __syncthreads();

    layer_full<NX, NF, true, 4>(g_Wo1T, bo1, s_x, s_h1, tid);
    __syncthreads();
    layer_full<NF, NF, true, 4>(g_Wo2T, bo2, s_h1, s_h2, tid);
    __syncthreads();
    layer_full<NF, NX, false, 2>(g_Wo3T, bo3, s_h2, s_x, tid);  // y -> s_x
    __syncthreads();

    // store y (coalesced)
    for (int idx = tid; idx < M2 * NX; idx += NTHREADS) {
        int r = idx >> 7, c = idx & (NX - 1);
        y_out[(R0 + r) * NX + c] =
            ((const float*)&s_x[(r >> 1) * NX + c])[r & 1];
    }
}

extern "C" void kernel_launch(void* const* d_in, const int* in_sizes, int n_in,
                              void* d_out, int out_size) {
    const float* input = (const float*)d_in[0];
    const float* x_step = (const float*)d_in[1];
    const float* dtp   = (const float*)d_in[2];
    const float* W_lin = (const float*)d_in[3];
    const float* W1    = (const float*)d_in[4];
    const float* b1    = (const float*)d_in[5];
    const float* W2    = (const float*)d_in[6];
    const float* b2    = (const float*)d_in[7];
    const float* W3    = (const float*)d_in[8];
    const float* b3    = (const float*)d_in[9];
    const float* Wo1   = (const float*)d_in[10];
    const float* bo1   = (const float*)d_in[11];
    const float* Wo2   = (const float*)d_in[12];
    const float* bo2   = (const float*)d_in[13];
    const float* Wo3   = (const float*)d_in[14];
    const float* bo3   = (const float*)d_in[15];

    float* out = (float*)d_out;
    float* y_out  = out;                               // [NT][NB][NX]
    float* xf_out = out + (size_t)NT * NB * NX;        // [NB][NX]

    static bool attr_done = false;
    if (!attr_done) {
        cudaFuncSetAttribute(ode_kernel,
                             cudaFuncAttributeMaxDynamicSharedMemorySize,
                             SMEM1_BYTES);
        cudaFuncSetAttribute(out_kernel,
                             cudaFuncAttributeMaxDynamicSharedMemorySize,
                             SMEM2_BYTES);
        attr_done = true;
    }

    prep_kernel<<<256, 256>>>(W_lin, W1, W2, W3, Wo1, Wo2, Wo3);
    ode_kernel<<<NCTA, NTHREADS, SMEM1_BYTES>>>(input, x_step, dtp,
                                                b1, b2, b3, xf_out);
    out_kernel<<<NCTA2, NTHREADS, SMEM2_BYTES>>>(bo1, bo2, bo3, y_out);
}

// round 10
// speedup vs baseline: 2.0928x; 1.0522x over previous
#include <cuda_runtime.h>

// ---------------------------------------------------------------------------
// ODELayer RK4 scan, Round 9.
// Phase 1: dx_net scan, 128 CTAs x 8 rows, 512 thr. Changes vs R7:
//   - deep-unrolled mainloops (kill periodic LDG stalls)
//   - W1+W_lin fused into one sync pair (both read z)
//   - RK4 update fused into W3 reduction epilogue; ks kept in a register
// Phase 2: out_net as big-M batched MLP (unchanged structure, unroll 4).
// fp32 packed f32x2 FMA throughout.
// ---------------------------------------------------------------------------

#define NU   32
#define NX   128
#define NF   256
#define NIN  160
#define NT   256
#define NB   1024
#define ROWS 8
#define NCTA (NB / ROWS)   // 128
#define NTHREADS 512

#define M2   64
#define P2   (M2 / 2)
#define NCTA2 ((NT * NB) / M2)   // 4096

// phase1 smem (float2): ze 640 + h1 1024 + h2 1024 + lin 512 + x 512 +
// pA 8192 + pB 8192 = 20096 f2 = 157 KB
#define SMEM1_F2   (4*NIN + 4*NF + 4*NF + 4*NX + 4*NX + 8192 + 8192)
#define SMEM1_BYTES (SMEM1_F2 * 8)
#define SMEM2_F2   (P2*NX + P2*NF + P2*NF)
#define SMEM2_BYTES (SMEM2_F2 * 8)

__device__ float g_xhist[(size_t)NT * NB * NX];

__device__ float g_W1T[NIN * NF];
__device__ float g_WlT[NIN * NX];
__device__ float g_W2T[NF * NF];
__device__ float g_W3T[NF * NX];
__device__ float g_Wo1T[NX * NF];
__device__ float g_Wo2T[NF * NF];
__device__ float g_Wo3T[NF * NX];

using ull = unsigned long long;

__device__ __forceinline__ ull pack2(float w) {
    ull r;
    asm("mov.b64 %0, {%1, %1};" : "=l"(r) : "f"(w));
    return r;
}
__device__ __forceinline__ void fma2(ull &d, ull a, ull b) {
    asm("fma.rn.f32x2 %0, %1, %2, %0;" : "+l"(d) : "l"(a), "l"(b));
}
__device__ __forceinline__ void addf2(ull &d, ull a) {
    asm("add.rn.f32x2 %0, %0, %1;" : "+l"(d) : "l"(a));
}
__device__ __forceinline__ float2 u2f(ull v) {
    float2 r;
    asm("mov.b64 {%0, %1}, %2;" : "=f"(r.x), "=f"(r.y) : "l"(v));
    return r;
}

// ---------------------------------------------------------------------------
// Phase-1 mainloop: thread computes 4 cols x 4 row-pairs on its K/S slice.
// N=256: G=64, S=8.  N=128: G=32, S=16.
// ---------------------------------------------------------------------------
template <int K, int N>
__device__ __forceinline__ void mainloop(const float* __restrict__ WT,
                                         const float2* __restrict__ src,
                                         ull* acc, int tid) {
    constexpr int G  = N / 4;
    constexpr int S  = NTHREADS / G;
    constexpr int KS = K / S;
    const int cg = tid & (G - 1);
    const int kg = tid / G;
    const int n0 = cg * 4;
#pragma unroll
    for (int i = 0; i < 16; ++i) acc[i] = 0;
    const float* wp = WT + n0;
    const int kbase = kg * KS;
#pragma unroll 8
    for (int kk = 0; kk < KS; kk += 2) {
        const int k = kbase + kk;
        float4 wa = __ldg(reinterpret_cast<const float4*>(wp + (size_t)k * N));
        float4 wb = __ldg(reinterpret_cast<const float4*>(wp + (size_t)(k + 1) * N));
        ull wa0 = pack2(wa.x), wa1 = pack2(wa.y), wa2 = pack2(wa.z), wa3 = pack2(wa.w);
        ull wb0 = pack2(wb.x), wb1 = pack2(wb.y), wb2 = pack2(wb.z), wb3 = pack2(wb.w);
#pragma unroll
        for (int p = 0; p < 4; ++p) {
            ulonglong2 z = *reinterpret_cast<const ulonglong2*>(src + (size_t)p * K + k);
            fma2(acc[p*4+0], z.x, wa0); fma2(acc[p*4+0], z.y, wb0);
            fma2(acc[p*4+1], z.x, wa1); fma2(acc[p*4+1], z.y, wb1);
            fma2(acc[p*4+2], z.x, wa2); fma2(acc[p*4+2], z.y, wb2);
            fma2(acc[p*4+3], z.x, wa3); fma2(acc[p*4+3], z.y, wb3);
        }
    }
}

template <int N>
__device__ __forceinline__ void store_part(float2* __restrict__ part,
                                           const ull* acc, int tid) {
    constexpr int G = N / 4;
    const int cg = tid & (G - 1);
    const int kg = tid / G;
    const int n0 = cg * 4;
    float2* pp = part + (size_t)kg * (4 * N);
#pragma unroll
    for (int p = 0; p < 4; ++p) {
        float2 a = u2f(acc[p*4+0]), b = u2f(acc[p*4+1]);
        float2 c = u2f(acc[p*4+2]), d = u2f(acc[p*4+3]);
        float4* q = reinterpret_cast<float4*>(pp + (size_t)p * N + n0);
        q[0] = make_float4(a.x, a.y, b.x, b.y);
        q[1] = make_float4(c.x, c.y, d.x, d.y);
    }
}

// reduce one N=256 layer: thread owns f2 elements {2*tid, 2*tid+1} of [4][256]
__device__ __forceinline__ void reduce256(const float2* __restrict__ part,  // 8 sets
                                          const float* __restrict__ bias,
                                          float2* __restrict__ dst, int tid) {
    const int j = 2 * tid;
    ull a0 = 0, a1 = 0, b0 = 0, b1 = 0;
#pragma unroll
    for (int s = 0; s < 8; s += 2) {
        ulonglong2 qa = *reinterpret_cast<const ulonglong2*>(part + (size_t)s * 1024 + j);
        ulonglong2 qb = *reinterpret_cast<const ulonglong2*>(part + (size_t)(s + 1) * 1024 + j);
        addf2(a0, qa.x); addf2(a1, qa.y);
        addf2(b0, qb.x); addf2(b1, qb.y);
    }
    addf2(a0, b0); addf2(a1, b1);
    const int col = j & (NF - 1);
    float2 v0 = u2f(a0), v1 = u2f(a1);
    float c0 = bias[col], c1 = bias[col + 1];
    v0.x = fmaxf(v0.x + c0, 0.f); v0.y = fmaxf(v0.y + c0, 0.f);
    v1.x = fmaxf(v1.x + c1, 0.f); v1.y = fmaxf(v1.y + c1, 0.f);
    *reinterpret_cast<float4*>(dst + j) = make_float4(v0.x, v0.y, v1.x, v1.y);
}

// reduce one N=128 layer (16 sets): returns thread's f2 element (index tid of [4][128])
__device__ __forceinline__ float2 reduce128(const float2* __restrict__ part, int tid) {
    ull a0 = 0, a1 = 0;
#pragma unroll
    for (int s = 0; s < 16; s += 2) {
        addf2(a0, *reinterpret_cast<const ull*>(part + (size_t)s * 512 + tid));
        addf2(a1, *reinterpret_cast<const ull*>(part + (size_t)(s + 1) * 512 + tid));
    }
    addf2(a0, a1);
    return u2f(a0);
}

// ---------------------------------------------------------------------------
// Phase-2 layer (big-M): full-K per thread, no reduction.
// ---------------------------------------------------------------------------
template <int K, int N, bool RELU, int PPT>
__device__ __forceinline__ void layer_full(const float* __restrict__ WT,
                                           const float* __restrict__ bias,
                                           const float2* __restrict__ src,
                                           float2* __restrict__ dst,
                                           int tid) {
    constexpr int G = N / 4;
    const int cg = tid & (G - 1);
    const int pg = tid / G;
    const int p0 = pg * PPT;
    const int n0 = cg * 4;
    ull acc[PPT * 4];
#pragma unroll
    for (int i = 0; i < PPT * 4; ++i) acc[i] = 0;
    const float* wp = WT + n0;
#pragma unroll 4
    for (int k = 0; k < K; k += 2) {
        float4 wa = __ldg(reinterpret_cast<const float4*>(wp + (size_t)k * N));
        float4 wb = __ldg(reinterpret_cast<const float4*>(wp + (size_t)(k + 1) * N));
        ull wa0 = pack2(wa.x), wa1 = pack2(wa.y), wa2 = pack2(wa.z), wa3 = pack2(wa.w);
        ull wb0 = pack2(wb.x), wb1 = pack2(wb.y), wb2 = pack2(wb.z), wb3 = pack2(wb.w);
#pragma unroll
        for (int p = 0; p < PPT; ++p) {
            ulonglong2 z = *reinterpret_cast<const ulonglong2*>(src + (size_t)(p0 + p) * K + k);
            fma2(acc[p*4+0], z.x, wa0); fma2(acc[p*4+0], z.y, wb0);
            fma2(acc[p*4+1], z.x, wa1); fma2(acc[p*4+1], z.y, wb1);
            fma2(acc[p*4+2], z.x, wa2); fma2(acc[p*4+2], z.y, wb2);
            fma2(acc[p*4+3], z.x, wa3); fma2(acc[p*4+3], z.y, wb3);
        }
    }
    float4 bv = __ldg(reinterpret_cast<const float4*>(bias + n0));
#pragma unroll
    for (int p = 0; p < PPT; ++p) {
        float2 v0 = u2f(acc[p*4+0]), v1 = u2f(acc[p*4+1]);
        float2 v2 = u2f(acc[p*4+2]), v3 = u2f(acc[p*4+3]);
        v0.x += bv.x; v0.y += bv.x;
        v1.x += bv.y; v1.y += bv.y;
        v2.x += bv.z; v2.y += bv.z;
        v3.x += bv.w; v3.y += bv.w;
        if (RELU) {
            v0.x = fmaxf(v0.x, 0.f); v0.y = fmaxf(v0.y, 0.f);
            v1.x = fmaxf(v1.x, 0.f); v1.y = fmaxf(v1.y, 0.f);
            v2.x = fmaxf(v2.x, 0.f); v2.y = fmaxf(v2.y, 0.f);
            v3.x = fmaxf(v3.x, 0.f); v3.y = fmaxf(v3.y, 0.f);
        }
        float4* q = reinterpret_cast<float4*>(dst + (size_t)(p0 + p) * N + n0);
        q[0] = make_float4(v0.x, v0.y, v1.x, v1.y);
        q[1] = make_float4(v2.x, v2.y, v3.x, v3.y);
    }
}

__global__ void prep_kernel(const float* __restrict__ W_lin, const float* __restrict__ W1,
                            const float* __restrict__ W2, const float* __restrict__ W3,
                            const float* __restrict__ Wo1, const float* __restrict__ Wo2,
                            const float* __restrict__ Wo3) {
    int i0 = blockIdx.x * blockDim.x + threadIdx.x;
    int stride = gridDim.x * blockDim.x;
    for (int j = i0; j < NF * NIN; j += stride) { int n = j / NIN, k = j % NIN; g_W1T[k * NF + n] = W1[j]; }
    for (int j = i0; j < NX * NIN; j += stride) { int m = j / NIN, k = j % NIN; g_WlT[k * NX + m] = W_lin[j]; }
    for (int j = i0; j < NF * NF;  j += stride) { int n = j / NF,  k = j % NF;  g_W2T[k * NF + n] = W2[j]; }
    for (int j = i0; j < NX * NF;  j += stride) { int m = j / NF,  k = j % NF;  g_W3T[k * NX + m] = W3[j]; }
    for (int j = i0; j < NF * NX;  j += stride) { int n = j / NX,  k = j % NX;  g_Wo1T[k * NF + n] = Wo1[j]; }
    for (int j = i0; j < NF * NF;  j += stride) { int n = j / NF,  k = j % NF;  g_Wo2T[k * NF + n] = Wo2[j]; }
    for (int j = i0; j < NF * NX;  j += stride) { int m = j / NF,  k = j % NF;  g_Wo3T[k * NX + m] = Wo3[j]; }
}

// ---------------------------------------------------------------------------
// Phase 1
// ---------------------------------------------------------------------------
__global__ void __launch_bounds__(NTHREADS, 1)
ode_kernel(const float* __restrict__ input,
           const float* __restrict__ x0,
           const float* __restrict__ dtp,
           const float* __restrict__ b1, const float* __restrict__ b2,
           const float* __restrict__ b3,
           float* __restrict__ xf_out)
{
    extern __shared__ __align__(16) char smem_raw[];
    float2* s_ze  = reinterpret_cast<float2*>(smem_raw);  // [4][NIN]
    float2* s_h1  = s_ze  + 4 * NIN;                      // [4][NF]
    float2* s_h2  = s_h1  + 4 * NF;                       // [4][NF]
    float2* s_lin = s_h2  + 4 * NF;                       // [4][NX]
    float2* s_x   = s_lin + 4 * NX;                       // [4][NX]
    float2* s_pA  = s_x   + 4 * NX;                       // 8 sets x 1024 f2
    float2* s_pB  = s_pA  + 8192;                         // 16 sets x 512 f2

    const int tid = threadIdx.x;
    const int rowbase = blockIdx.x * ROWS;
    const float dt = *dtp;
    const float dth = 0.5f * dt;
    const float dt6 = dt * (1.0f / 6.0f);

    // load x0 (pair-interleave rows)
    for (int idx = tid; idx < ROWS * NX; idx += NTHREADS) {
        int r = idx >> 7, c = idx & (NX - 1);
        float v = x0[(size_t)(rowbase + r) * NX + c];
        ((float*)&s_x[(r >> 1) * NX + c])[r & 1] = v;
    }
    __syncthreads();

    ull acc[16];
    const int zp = tid >> 7, zc = tid & (NX - 1);   // this thread's z-head slot

    for (int t = 0; t < NT; ++t) {
        // setup: u -> tail of z, x -> head of z
        if (tid < ROWS * NU) {
            int r = tid >> 5, c = tid & 31;
            float v = input[((size_t)t * NB + rowbase + r) * NU + c];
            ((float*)&s_ze[(r >> 1) * NIN + NX + c])[r & 1] = v;
        }
        s_ze[zp * NIN + zc] = s_x[tid];
        __syncthreads();

        float2 ks = make_float2(0.f, 0.f);

#pragma unroll 1
        for (int e = 0; e < 4; ++e) {
            // fused W1 + W_lin (both read s_ze)
            mainloop<NIN, NF>(g_W1T, s_ze, acc, tid);
            store_part<NF>(s_pA, acc, tid);
            mainloop<NIN, NX>(g_WlT, s_ze, acc, tid);
            store_part<NX>(s_pB, acc, tid);
            __syncthreads();
            reduce256(s_pA, b1, s_h1, tid);
            s_lin[tid] = reduce128(s_pB, tid);
            __syncthreads();

            // W2
            mainloop<NF, NF>(g_W2T, s_h1, acc, tid);
            store_part<NF>(s_pA, acc, tid);
            __syncthreads();
            reduce256(s_pA, b2, s_h2, tid);
            __syncthreads();

            // W3 + fused RK4 epilogue
            mainloop<NF, NX>(g_W3T, s_h2, acc, tid);
            store_part<NX>(s_pB, acc, tid);
            __syncthreads();
            {
                float2 kv = reduce128(s_pB, tid);
                const float bb = b3[zc];
                float2 lv = s_lin[tid];
                kv.x += lv.x + bb;
                kv.y += lv.y + bb;
                float2 xv = s_x[tid];
                if (e == 0) {
                    ks = kv;
                    s_ze[zp * NIN + zc] = make_float2(fmaf(dth, kv.x, xv.x),
                                                      fmaf(dth, kv.y, xv.y));
                } else if (e == 1) {
                    ks.x = fmaf(2.f, kv.x, ks.x); ks.y = fmaf(2.f, kv.y, ks.y);
                    s_ze[zp * NIN + zc] = make_float2(fmaf(dth, kv.x, xv.x),
                                                      fmaf(dth, kv.y, xv.y));
                } else if (e == 2) {
                    ks.x = fmaf(2.f, kv.x, ks.x); ks.y = fmaf(2.f, kv.y, ks.y);
                    s_ze[zp * NIN + zc] = make_float2(fmaf(dt, kv.x, xv.x),
                                                      fmaf(dt, kv.y, xv.y));
                } else {
                    ks.x += kv.x; ks.y += kv.y;
                    s_x[tid] = make_float2(fmaf(dt6, ks.x, xv.x),
                                           fmaf(dt6, ks.y, xv.y));
                }
            }
            __syncthreads();
        }

        // store x_{t+1} history (coalesced); next setup reads s_x / writes s_ze
        for (int idx = tid; idx < ROWS * NX; idx += NTHREADS) {
            int r = idx >> 7, c = idx & (NX - 1);
            float v = ((const float*)&s_x[(r >> 1) * NX + c])[r & 1];
            g_xhist[((size_t)t * NB + rowbase + r) * NX + c] = v;
        }
    }

    __syncthreads();
    for (int idx = tid; idx < ROWS * NX; idx += NTHREADS) {
        int r = idx >> 7, c = idx & (NX - 1);
        xf_out[(size_t)(rowbase + r) * NX + c] =
            ((const float*)&s_x[(r >> 1) * NX + c])[r & 1];
    }
}

// ---------------------------------------------------------------------------
// Phase 2
// ---------------------------------------------------------------------------
__global__ void __launch_bounds__(NTHREADS, 1)
out_kernel(const float* __restrict__ bo1, const float* __restrict__ bo2,
           const float* __restrict__ bo3,
           float* __restrict__ y_out)
{
    extern __shared__ __align__(16) char smem_raw[];
    float2* s_x  = reinterpret_cast<float2*>(smem_raw);  // [P2][NX]
    float2* s_h1 = s_x  + P2 * NX;                       // [P2][NF]
    float2* s_h2 = s_h1 + P2 * NF;                       // [P2][NF]

    const int tid = threadIdx.x;
    const size_t R0 = (size_t)blockIdx.x * M2;

    for (int idx = tid; idx < M2 * NX; idx += NTHREADS) {
        int r = idx >> 7, c = idx & (NX - 1);
        float v = g_xhist[(R0 + r) * NX + c];
        ((float*)&s_x[(r >> 1) * NX + c])[r & 1] = v;
    }
    __syncthreads();

    layer_full<NX, NF, true, 4>(g_Wo1T, bo1, s_x, s_h1, tid);
    __syncthreads();
    layer_full<NF, NF, true, 4>(g_Wo2T, bo2, s_h1, s_h2, tid);
    __syncthreads();
    layer_full<NF, NX, false, 2>(g_Wo3T, bo3, s_h2, s_x, tid);
    __syncthreads();

    for (int idx = tid; idx < M2 * NX; idx += NTHREADS) {
        int r = idx >> 7, c = idx & (NX - 1);
        y_out[(R0 + r) * NX + c] =
            ((const float*)&s_x[(r >> 1) * NX + c])[r & 1];
    }
}

extern "C" void kernel_launch(void* const* d_in, const int* in_sizes, int n_in,
                              void* d_out, int out_size) {
    const float* input = (const float*)d_in[0];
    const float* x_step = (const float*)d_in[1];
    const float* dtp   = (const float*)d_in[2];
    const float* W_lin = (const float*)d_in[3];
    const float* W1    = (const float*)d_in[4];
    const float* b1    = (const float*)d_in[5];
    const float* W2    = (const float*)d_in[6];
    const float* b2    = (const float*)d_in[7];
    const float* W3    = (const float*)d_in[8];
    const float* b3    = (const float*)d_in[9];
    const float* Wo1   = (const float*)d_in[10];
    const float* bo1   = (const float*)d_in[11];
    const float* Wo2   = (const float*)d_in[12];
    const float* bo2   = (const float*)d_in[13];
    const float* Wo3   = (const float*)d_in[14];
    const float* bo3   = (const float*)d_in[15];

    float* out = (float*)d_out;
    float* y_out  = out;
    float* xf_out = out + (size_t)NT * NB * NX;

    static bool attr_done = false;
    if (!attr_done) {
        cudaFuncSetAttribute(ode_kernel,
                             cudaFuncAttributeMaxDynamicSharedMemorySize,
                             SMEM1_BYTES);
        cudaFuncSetAttribute(out_kernel,
                             cudaFuncAttributeMaxDynamicSharedMemorySize,
                             SMEM2_BYTES);
        attr_done = true;
    }

    prep_kernel<<<256, 256>>>(W_lin, W1, W2, W3, Wo1, Wo2, Wo3);
    ode_kernel<<<NCTA, NTHREADS, SMEM1_BYTES>>>(input, x_step, dtp,
                                                b1, b2, b3, xf_out);
    out_kernel<<<NCTA2, NTHREADS, SMEM2_BYTES>>>(bo1, bo2, bo3, y_out);
}